// round 6
// baseline (speedup 1.0000x reference)
#include <cuda_runtime.h>
#include <cuda_fp16.h>

// BSplineLayer: piecewise-linear spline eval.
// u: [4096, 64, 256] f32 (flat, channel = i % 256)
// knots: [256, 64] sorted ascending per channel; coefs: [256, 64].
// out = c0 + (x-k0)/(k1-k0+1e-6) * (c1-c0), segment via searchsorted-left.
//
// Fast path (knots affine per channel, runtime-verified):
//  - float4 I/O, 8 elements (2 float4) per thread per iteration
//  - j computed in registers; ONE LDS.32 of half2(c0, dc*scale) per element
//  - scale = h/(h+eps) folded into dc at table build
//  - 512 threads x 3 CTAs/SM = 48 warps; 32-bit indexing throughout

#define M_CH    256
#define K_KNOTS 64
#define N_SEG   63
#define EPS     1e-6f

// smem: float2 sparam[256] (invh, b) | half2 sseg[256*64] | int flag
#define SMEM_BYTES (256 * 8 + 256 * 64 * 4 + 16)

__global__ __launch_bounds__(512, 3)
void bspline_kernel(const float* __restrict__ u,
                    const float* __restrict__ knots,
                    const float* __restrict__ coefs,
                    float* __restrict__ out,
                    int n4 /* number of float4 elements */)
{
    extern __shared__ char smem_raw[];
    float2*  sparam = (float2*)smem_raw;                      // [256] (invh, b)
    __half2* sseg   = (__half2*)(smem_raw + 256 * 8);         // [256][64] (c0, dc*scale)
    int*     sflag  = (int*)(smem_raw + 256 * 8 + 256 * 64 * 4);

    const int tid = threadIdx.x;
    if (tid == 0) *sflag = 0;
    __syncthreads();

    // ---- stage coef segments: sseg[c*64+j] = half2(c_j, (c_{j+1}-c_j)*scale_c) ----
    for (int i = tid; i < M_CH * K_KNOTS; i += blockDim.x) {
        int j = i & 63;
        if (j < N_SEG) {
            int c = i >> 6;
            float k0 = knots[c * K_KNOTS];
            float kl = knots[c * K_KNOTS + K_KNOTS - 1];
            float h  = (kl - k0) * (1.0f / (float)N_SEG);
            float scale = h / (h + EPS);
            float c0 = coefs[c * K_KNOTS + j];
            float c1 = coefs[c * K_KNOTS + j + 1];
            sseg[i] = __floats2half2_rn(c0, (c1 - c0) * scale);
        }
    }

    // ---- per-channel affine params + uniformity check ----
    if (tid < M_CH) {
        const int c = tid;
        const float* kc = knots + c * K_KNOTS;
        float k0 = kc[0];
        float kl = kc[K_KNOTS - 1];
        float h  = (kl - k0) * (1.0f / (float)N_SEG);
        float invh = (float)N_SEG / (kl - k0);
        float tol = 1e-4f * fabsf(h) + 1e-30f;
        bool bad = !(h > 0.0f);
        #pragma unroll 4
        for (int j = 1; j < K_KNOTS - 1; j++) {
            float pred = fmaf((float)j, h, k0);
            if (fabsf(kc[j] - pred) > tol) { bad = true; break; }
        }
        if (bad) *sflag = 1;
        sparam[c] = make_float2(invh, -k0 * invh);
    }
    __syncthreads();

    const bool affine = (*sflag == 0);

    const float4* __restrict__ u4 = (const float4*)u;
    float4*       __restrict__ o4 = (float4*)out;
    const int gtid   = blockIdx.x * blockDim.x + tid;
    const int stride = blockDim.x * gridDim.x;   // float4 stride; 4*stride % 256 == 0
    // channels of this thread's float4: cb..cb+3, fixed across iterations
    const int cb     = (gtid << 2) & (M_CH - 1);

    if (affine) {
        // preload 4 channel params (invh, b) into registers
        float p_invh[4], p_b[4];
        #pragma unroll
        for (int i = 0; i < 4; i++) {
            float2 p = sparam[cb + i];
            p_invh[i] = p.x; p_b[i] = p.y;
        }
        const __half2* __restrict__ segbase = sseg + (cb << 6);

        for (int f = gtid; f < n4; f += 2 * stride) {
            const int  f2   = f + stride;
            const bool has2 = (f2 < n4);

            float4 a = u4[f];
            float4 b = has2 ? u4[f2] : a;   // MLP: both loads in flight

            float xa[4] = {a.x, a.y, a.z, a.w};
            float xb[4] = {b.x, b.y, b.z, b.w};
            float ra[4], rb[4];

            #pragma unroll
            for (int i = 0; i < 4; i++) {
                float s  = fmaf(xa[i], p_invh[i], p_b[i]);
                float jf = floorf(s);
                jf = fminf(fmaxf(jf, 0.0f), (float)(N_SEG - 1));
                float2 cd = __half22float2(segbase[(i << 6) + (int)jf]);
                ra[i] = fmaf(s - jf, cd.y, cd.x);
            }
            #pragma unroll
            for (int i = 0; i < 4; i++) {
                float s  = fmaf(xb[i], p_invh[i], p_b[i]);
                float jf = floorf(s);
                jf = fminf(fmaxf(jf, 0.0f), (float)(N_SEG - 1));
                float2 cd = __half22float2(segbase[(i << 6) + (int)jf]);
                rb[i] = fmaf(s - jf, cd.y, cd.x);
            }

            o4[f] = make_float4(ra[0], ra[1], ra[2], ra[3]);
            if (has2)
                o4[f2] = make_float4(rb[0], rb[1], rb[2], rb[3]);
        }
    } else {
        // generic fallback: exact searchsorted-left via binary search, f32 math
        for (int f = gtid; f < n4; f += stride) {
            float4 a = u4[f];
            float x[4] = {a.x, a.y, a.z, a.w};
            float r[4];
            #pragma unroll
            for (int i = 0; i < 4; i++) {
                const int c = cb + i;
                const float* kc = knots + c * K_KNOTS;
                const float xi = x[i];
                int lo = 0, hi = K_KNOTS;
                while (lo < hi) {
                    int mid = (lo + hi) >> 1;
                    if (__ldg(kc + mid) < xi) lo = mid + 1; else hi = mid;
                }
                int j = min(max(lo - 1, 0), N_SEG - 1);
                float k0 = __ldg(kc + j);
                float k1 = __ldg(kc + j + 1);
                float c0 = __ldg(coefs + c * K_KNOTS + j);
                float c1 = __ldg(coefs + c * K_KNOTS + j + 1);
                float tt = (xi - k0) / (k1 - k0 + EPS);
                r[i] = fmaf(tt, c1 - c0, c0);
            }
            o4[f] = make_float4(r[0], r[1], r[2], r[3]);
        }
    }
}

extern "C" void kernel_launch(void* const* d_in, const int* in_sizes, int n_in,
                              void* d_out, int out_size)
{
    const float* u     = (const float*)d_in[0];
    const float* knots = (const float*)d_in[1];
    const float* coefs = (const float*)d_in[2];
    float*       out   = (float*)d_out;

    const int n  = in_sizes[0];   // 67,108,864 (divisible by 4)
    const int n4 = n >> 2;

    static_assert(SMEM_BYTES * 3 <= 227 * 1024, "need 3 CTAs/SM");
    cudaFuncSetAttribute(bspline_kernel,
                         cudaFuncAttributeMaxDynamicSharedMemorySize, SMEM_BYTES);

    int dev = 0, nsm = 148;
    cudaGetDevice(&dev);
    cudaDeviceGetAttribute(&nsm, cudaDevAttrMultiProcessorCount, dev);

    bspline_kernel<<<3 * nsm, 512, SMEM_BYTES>>>(u, knots, coefs, out, n4);
}

// round 7
// speedup vs baseline: 1.1538x; 1.1538x over previous
#include <cuda_runtime.h>
#include <cuda_fp16.h>

// BSplineLayer: piecewise-linear spline eval.
// u: [4096, 64, 256] f32 (flat, channel = i % 256)
// knots: [256, 64] sorted ascending per channel; coefs: [256, 64].
// out = c0 + (x-k0)/(k1-k0+1e-6) * (c1-c0), segment via searchsorted-left.
//
// Fast path (knots affine per channel, runtime-verified):
//  - float4 I/O, 8 elems (2 unpredicated strided float4) per thread per iter
//  - coef table in smem with PERMUTED layout sseg[(j<<8) + (c>>2) + ((c&3)<<6)]
//    -> LDS bank = lane id, ZERO conflicts regardless of data-dependent j
//  - ONE LDS.32 of half2(c0, dc*scale) per element; scale folded at build
//  - 512 threads x 3 CTAs/SM = 48 warps

#define M_CH    256
#define K_KNOTS 64
#define N_SEG   63
#define EPS     1e-6f

// smem: float2 sparam[256] (invh, b) | half2 sseg[64*256] permuted | int flag
#define SMEM_BYTES (256 * 8 + 64 * 256 * 4 + 16)

__global__ __launch_bounds__(512, 3)
void bspline_kernel(const float* __restrict__ u,
                    const float* __restrict__ knots,
                    const float* __restrict__ coefs,
                    float* __restrict__ out,
                    int n4 /* number of float4 elements */)
{
    extern __shared__ char smem_raw[];
    float2*  sparam = (float2*)smem_raw;                  // [256] (invh, b)
    __half2* sseg   = (__half2*)(smem_raw + 256 * 8);     // [64][256] permuted cols
    int*     sflag  = (int*)(smem_raw + 256 * 8 + 64 * 256 * 4);

    const int tid = threadIdx.x;
    if (tid == 0) *sflag = 0;
    __syncthreads();

    // ---- stage coef segments, permuted: col(c) = (c>>2) + ((c&3)<<6) ----
    for (int i = tid; i < M_CH * K_KNOTS; i += blockDim.x) {
        int j = i & 63;
        if (j < N_SEG) {
            int c = i >> 6;
            float k0 = knots[c * K_KNOTS];
            float kl = knots[c * K_KNOTS + K_KNOTS - 1];
            float h  = (kl - k0) * (1.0f / (float)N_SEG);
            float scale = h / (h + EPS);
            float c0 = coefs[c * K_KNOTS + j];
            float c1 = coefs[c * K_KNOTS + j + 1];
            int col = (c >> 2) + ((c & 3) << 6);
            sseg[(j << 8) + col] = __floats2half2_rn(c0, (c1 - c0) * scale);
        }
    }

    // ---- per-channel affine params + uniformity check ----
    if (tid < M_CH) {
        const int c = tid;
        const float* kc = knots + c * K_KNOTS;
        float k0 = kc[0];
        float kl = kc[K_KNOTS - 1];
        float h  = (kl - k0) * (1.0f / (float)N_SEG);
        float invh = (float)N_SEG / (kl - k0);
        float tol = 1e-4f * fabsf(h) + 1e-30f;
        bool bad = !(h > 0.0f);
        #pragma unroll 4
        for (int j = 1; j < K_KNOTS - 1; j++) {
            float pred = fmaf((float)j, h, k0);
            if (fabsf(kc[j] - pred) > tol) { bad = true; break; }
        }
        if (bad) *sflag = 1;
        sparam[c] = make_float2(invh, -k0 * invh);
    }
    __syncthreads();

    const bool affine = (*sflag == 0);

    const float4* __restrict__ u4 = (const float4*)u;
    float4*       __restrict__ o4 = (float4*)out;
    const int gtid   = blockIdx.x * blockDim.x + tid;
    const int stride = blockDim.x * gridDim.x;   // float4 stride; 4*stride % 256 == 0
    const int cb     = (gtid << 2) & (M_CH - 1); // this thread's 4 channels, fixed

    if (affine) {
        // preload 4 channel params (invh, b)
        float p_invh[4], p_b[4];
        #pragma unroll
        for (int i = 0; i < 4; i++) {
            float2 p = sparam[cb + i];
            p_invh[i] = p.x; p_b[i] = p.y;
        }
        // per-slot table base: col = (cb>>2) + (i<<6); bank = lane -> conflict-free
        const __half2* __restrict__ seg0 = sseg + (cb >> 2);

        int f = gtid;
        const int lim = n4 - stride;   // room for the pair
        for (; f < lim; f += 2 * stride) {
            const int f2 = f + stride;
            float4 a = u4[f];          // both loads unpredicated, batched
            float4 b = u4[f2];

            float xa[4] = {a.x, a.y, a.z, a.w};
            float xb[4] = {b.x, b.y, b.z, b.w};
            float ra[4], rb[4];

            #pragma unroll
            for (int i = 0; i < 4; i++) {
                float s  = fmaf(xa[i], p_invh[i], p_b[i]);
                float jf = floorf(s);
                jf = fminf(fmaxf(jf, 0.0f), (float)(N_SEG - 1));
                int  ji = (int)jf;
                float2 cd = __half22float2(seg0[(ji << 8) + (i << 6)]);
                ra[i] = fmaf(s - jf, cd.y, cd.x);
            }
            #pragma unroll
            for (int i = 0; i < 4; i++) {
                float s  = fmaf(xb[i], p_invh[i], p_b[i]);
                float jf = floorf(s);
                jf = fminf(fmaxf(jf, 0.0f), (float)(N_SEG - 1));
                int  ji = (int)jf;
                float2 cd = __half22float2(seg0[(ji << 8) + (i << 6)]);
                rb[i] = fmaf(s - jf, cd.y, cd.x);
            }

            o4[f]  = make_float4(ra[0], ra[1], ra[2], ra[3]);
            o4[f2] = make_float4(rb[0], rb[1], rb[2], rb[3]);
        }
        // tail: single float4s, unpredicated loop
        for (; f < n4; f += stride) {
            float4 a = u4[f];
            float x[4] = {a.x, a.y, a.z, a.w};
            float r[4];
            #pragma unroll
            for (int i = 0; i < 4; i++) {
                float s  = fmaf(x[i], p_invh[i], p_b[i]);
                float jf = floorf(s);
                jf = fminf(fmaxf(jf, 0.0f), (float)(N_SEG - 1));
                int  ji = (int)jf;
                float2 cd = __half22float2(seg0[(ji << 8) + (i << 6)]);
                r[i] = fmaf(s - jf, cd.y, cd.x);
            }
            o4[f] = make_float4(r[0], r[1], r[2], r[3]);
        }
    } else {
        // generic fallback: exact searchsorted-left via binary search, f32 math
        for (int f = gtid; f < n4; f += stride) {
            float4 a = u4[f];
            float x[4] = {a.x, a.y, a.z, a.w};
            float r[4];
            #pragma unroll
            for (int i = 0; i < 4; i++) {
                const int c = cb + i;
                const float* kc = knots + c * K_KNOTS;
                const float xi = x[i];
                int lo = 0, hi = K_KNOTS;
                while (lo < hi) {
                    int mid = (lo + hi) >> 1;
                    if (__ldg(kc + mid) < xi) lo = mid + 1; else hi = mid;
                }
                int j = min(max(lo - 1, 0), N_SEG - 1);
                float k0 = __ldg(kc + j);
                float k1 = __ldg(kc + j + 1);
                float c0 = __ldg(coefs + c * K_KNOTS + j);
                float c1 = __ldg(coefs + c * K_KNOTS + j + 1);
                float tt = (xi - k0) / (k1 - k0 + EPS);
                r[i] = fmaf(tt, c1 - c0, c0);
            }
            o4[f] = make_float4(r[0], r[1], r[2], r[3]);
        }
    }
}

extern "C" void kernel_launch(void* const* d_in, const int* in_sizes, int n_in,
                              void* d_out, int out_size)
{
    const float* u     = (const float*)d_in[0];
    const float* knots = (const float*)d_in[1];
    const float* coefs = (const float*)d_in[2];
    float*       out   = (float*)d_out;

    const int n  = in_sizes[0];   // 67,108,864 (divisible by 4)
    const int n4 = n >> 2;

    static_assert(SMEM_BYTES * 3 <= 227 * 1024, "need 3 CTAs/SM");
    cudaFuncSetAttribute(bspline_kernel,
                         cudaFuncAttributeMaxDynamicSharedMemorySize, SMEM_BYTES);

    int dev = 0, nsm = 148;
    cudaGetDevice(&dev);
    cudaDeviceGetAttribute(&nsm, cudaDevAttrMultiProcessorCount, dev);

    bspline_kernel<<<3 * nsm, 512, SMEM_BYTES>>>(u, knots, coefs, out, n4);
}

// round 8
// speedup vs baseline: 1.3135x; 1.1384x over previous
#include <cuda_runtime.h>
#include <cuda_fp16.h>

// BSplineLayer: piecewise-linear spline eval.
// u: [4096, 64, 256] f32 (flat, channel = i % 256)
// knots: [256, 64] sorted ascending per channel; coefs: [256, 64].
// out = c0 + (x-k0)/(k1-k0+1e-6) * (c1-c0), segment via searchsorted-left.
//
// Fast path (knots affine per channel, runtime-verified):
//  - 1024 threads, 1 CTA/SM, 64-reg budget (R3 shape: the proven fastest)
//  - 16 elems/thread/iter via 4 consecutive-pair LDG.128, all issued up front
//  - coef table permuted: sseg[(j<<8) + (c>>3) + ((c&7)<<5)] -> for the
//    8-consecutive-channel mapping, LDS bank == lane id: ZERO conflicts
//  - ONE LDS.32 of half2(c0, dc*scale) per element; scale folded at build

#define M_CH    256
#define K_KNOTS 64
#define N_SEG   63
#define EPS     1e-6f

#define COLP(c) (((c) >> 3) + (((c) & 7) << 5))

// smem: float2 sparam[256] (invh, b) | half2 sseg[64*256] permuted | int flag
#define SMEM_BYTES (256 * 8 + 64 * 256 * 4 + 16)

__global__ __launch_bounds__(1024, 1)
void bspline_kernel(const float* __restrict__ u,
                    const float* __restrict__ knots,
                    const float* __restrict__ coefs,
                    float* __restrict__ out,
                    int n8 /* number of 8-element groups */)
{
    extern __shared__ char smem_raw[];
    float2*  sparam = (float2*)smem_raw;                  // [256] (invh, b)
    __half2* sseg   = (__half2*)(smem_raw + 256 * 8);     // [64][256] permuted
    int*     sflag  = (int*)(smem_raw + 256 * 8 + 64 * 256 * 4);

    const int tid = threadIdx.x;
    if (tid == 0) *sflag = 0;
    __syncthreads();

    // ---- stage coef segments, permuted: col(c) = (c>>3) + ((c&7)<<5) ----
    for (int i = tid; i < M_CH * K_KNOTS; i += blockDim.x) {
        int j = i & 63;
        if (j < N_SEG) {
            int c = i >> 6;
            float k0 = knots[c * K_KNOTS];
            float kl = knots[c * K_KNOTS + K_KNOTS - 1];
            float h  = (kl - k0) * (1.0f / (float)N_SEG);
            float scale = h / (h + EPS);
            float c0 = coefs[c * K_KNOTS + j];
            float c1 = coefs[c * K_KNOTS + j + 1];
            sseg[(j << 8) + COLP(c)] = __floats2half2_rn(c0, (c1 - c0) * scale);
        }
    }

    // ---- per-channel affine params + uniformity check ----
    if (tid < M_CH) {
        const int c = tid;
        const float* kc = knots + c * K_KNOTS;
        float k0 = kc[0];
        float kl = kc[K_KNOTS - 1];
        float h  = (kl - k0) * (1.0f / (float)N_SEG);
        float invh = (float)N_SEG / (kl - k0);
        float tol = 1e-4f * fabsf(h) + 1e-30f;
        bool bad = !(h > 0.0f);
        #pragma unroll 4
        for (int j = 1; j < K_KNOTS - 1; j++) {
            float pred = fmaf((float)j, h, k0);
            if (fabsf(kc[j] - pred) > tol) { bad = true; break; }
        }
        if (bad) *sflag = 1;
        sparam[c] = make_float2(invh, -k0 * invh);
    }
    __syncthreads();

    const bool affine = (*sflag == 0);

    const float4* __restrict__ u4 = (const float4*)u;
    float4*       __restrict__ o4 = (float4*)out;
    const int gtid = blockIdx.x * blockDim.x + tid;
    const int S    = blockDim.x * gridDim.x;     // group stride; 8S % 256 == 0
    const int cb   = (gtid << 3) & (M_CH - 1);   // channels cb..cb+7, fixed

    if (affine) {
        // preload 8 channel params (invh, b)
        float p_invh[8], p_b[8];
        #pragma unroll
        for (int i = 0; i < 8; i++) {
            float2 p = sparam[cb + i];
            p_invh[i] = p.x; p_b[i] = p.y;
        }
        // table base for this thread: + (i<<5) + (j<<8) per access
        const __half2* __restrict__ seg0 = sseg + (cb >> 3);

        int g = gtid;
        // main loop: two groups per iteration (g and g+S), 4 LDG.128 up front
        for (; g + S < n8; g += 2 * S) {
            const int g2 = g + S;
            float4 a0 = u4[2 * g];
            float4 a1 = u4[2 * g + 1];
            float4 b0 = u4[2 * g2];
            float4 b1 = u4[2 * g2 + 1];

            float xa[8] = {a0.x, a0.y, a0.z, a0.w, a1.x, a1.y, a1.z, a1.w};
            float xb[8] = {b0.x, b0.y, b0.z, b0.w, b1.x, b1.y, b1.z, b1.w};
            float ra[8], rb[8];

            #pragma unroll
            for (int i = 0; i < 8; i++) {
                float s  = fmaf(xa[i], p_invh[i], p_b[i]);
                float jf = floorf(s);
                jf = fminf(fmaxf(jf, 0.0f), (float)(N_SEG - 1));
                float2 cd = __half22float2(seg0[((int)jf << 8) + (i << 5)]);
                ra[i] = fmaf(s - jf, cd.y, cd.x);
            }
            #pragma unroll
            for (int i = 0; i < 8; i++) {
                float s  = fmaf(xb[i], p_invh[i], p_b[i]);
                float jf = floorf(s);
                jf = fminf(fmaxf(jf, 0.0f), (float)(N_SEG - 1));
                float2 cd = __half22float2(seg0[((int)jf << 8) + (i << 5)]);
                rb[i] = fmaf(s - jf, cd.y, cd.x);
            }

            o4[2 * g]      = make_float4(ra[0], ra[1], ra[2], ra[3]);
            o4[2 * g + 1]  = make_float4(ra[4], ra[5], ra[6], ra[7]);
            o4[2 * g2]     = make_float4(rb[0], rb[1], rb[2], rb[3]);
            o4[2 * g2 + 1] = make_float4(rb[4], rb[5], rb[6], rb[7]);
        }
        // tail: one group at a time
        for (; g < n8; g += S) {
            float4 a0 = u4[2 * g];
            float4 a1 = u4[2 * g + 1];
            float x[8] = {a0.x, a0.y, a0.z, a0.w, a1.x, a1.y, a1.z, a1.w};
            float r[8];
            #pragma unroll
            for (int i = 0; i < 8; i++) {
                float s  = fmaf(x[i], p_invh[i], p_b[i]);
                float jf = floorf(s);
                jf = fminf(fmaxf(jf, 0.0f), (float)(N_SEG - 1));
                float2 cd = __half22float2(seg0[((int)jf << 8) + (i << 5)]);
                r[i] = fmaf(s - jf, cd.y, cd.x);
            }
            o4[2 * g]     = make_float4(r[0], r[1], r[2], r[3]);
            o4[2 * g + 1] = make_float4(r[4], r[5], r[6], r[7]);
        }
    } else {
        // generic fallback: exact searchsorted-left via binary search, f32 math
        for (int g = gtid; g < n8; g += S) {
            float4 a0 = u4[2 * g];
            float4 a1 = u4[2 * g + 1];
            float x[8] = {a0.x, a0.y, a0.z, a0.w, a1.x, a1.y, a1.z, a1.w};
            float r[8];
            #pragma unroll
            for (int i = 0; i < 8; i++) {
                const int c = cb + i;
                const float* kc = knots + c * K_KNOTS;
                const float xi = x[i];
                int lo = 0, hi = K_KNOTS;
                while (lo < hi) {
                    int mid = (lo + hi) >> 1;
                    if (__ldg(kc + mid) < xi) lo = mid + 1; else hi = mid;
                }
                int j = min(max(lo - 1, 0), N_SEG - 1);
                float k0 = __ldg(kc + j);
                float k1 = __ldg(kc + j + 1);
                float c0 = __ldg(coefs + c * K_KNOTS + j);
                float c1 = __ldg(coefs + c * K_KNOTS + j + 1);
                float tt = (xi - k0) / (k1 - k0 + EPS);
                r[i] = fmaf(tt, c1 - c0, c0);
            }
            o4[2 * g]     = make_float4(r[0], r[1], r[2], r[3]);
            o4[2 * g + 1] = make_float4(r[4], r[5], r[6], r[7]);
        }
    }
}

extern "C" void kernel_launch(void* const* d_in, const int* in_sizes, int n_in,
                              void* d_out, int out_size)
{
    const float* u     = (const float*)d_in[0];
    const float* knots = (const float*)d_in[1];
    const float* coefs = (const float*)d_in[2];
    float*       out   = (float*)d_out;

    const int n  = in_sizes[0];   // 67,108,864 (divisible by 8)
    const int n8 = n >> 3;

    static_assert(SMEM_BYTES <= 227 * 1024, "smem over sm_103a limit");
    cudaFuncSetAttribute(bspline_kernel,
                         cudaFuncAttributeMaxDynamicSharedMemorySize, SMEM_BYTES);

    int dev = 0, nsm = 148;
    cudaGetDevice(&dev);
    cudaDeviceGetAttribute(&nsm, cudaDevAttrMultiProcessorCount, dev);

    bspline_kernel<<<nsm, 1024, SMEM_BYTES>>>(u, knots, coefs, out, n8);
}

// round 9
// speedup vs baseline: 1.6219x; 1.2348x over previous
#include <cuda_runtime.h>

// BSplineLayer: piecewise-linear spline eval.
// u: [4096, 64, 256] f32 (flat, channel = i % 256)
// knots: [256, 64] sorted ascending per channel; coefs: [256, 64].
// out = c0 + (x-k0)/(k1-k0+1e-6) * (c1-c0), segment via searchsorted-left.
//
// This round = R3 (fastest so far) with ONE change: the coef table is stored
// permuted, sseg[(j<<8) + (c>>3) + ((c&7)<<5)], so that with the
// 8-consecutive-channels-per-thread mapping the LDS.64 bank-pair equals
// 2*lane mod 32 -> conflict-free (exactly the 2-phase LDS.64 minimum),
// independent of the data-dependent segment index j.
// Everything else (loop shape, fp32 table, 1024x1 CTA) is R3 verbatim.

#define M_CH    256
#define K_KNOTS 64
#define N_SEG   63
#define EPS     1e-6f

#define COLP(c) (((c) >> 3) + (((c) & 7) << 5))

// smem: float4 sparam[256] | float2 sseg[64*256] permuted | int flag
#define SMEM_BYTES (256 * 16 + 64 * 256 * 8 + 16)

__global__ __launch_bounds__(1024, 1)
void bspline_kernel(const float* __restrict__ u,
                    const float* __restrict__ knots,
                    const float* __restrict__ coefs,
                    float* __restrict__ out,
                    int n8 /* groups of 8 elements */)
{
    extern __shared__ char smem_raw[];
    float4* sparam = (float4*)smem_raw;                       // [256] (invh, b, scale, 0)
    float2* sseg   = (float2*)(smem_raw + 256 * 16);          // [64][256] permuted (c0, dc)
    int*    sflag  = (int*)(smem_raw + 256 * 16 + 64 * 256 * 8);

    const int tid = threadIdx.x;

    if (tid == 0) *sflag = 0;
    __syncthreads();

    // ---- stage coef segments, permuted: sseg[(j<<8)+COLP(c)] = (c_j, dc_j) ----
    for (int i = tid; i < M_CH * K_KNOTS; i += blockDim.x) {
        int j = i & 63;
        if (j < N_SEG) {
            int c = i >> 6;
            float c0 = coefs[c * K_KNOTS + j];
            float c1 = coefs[c * K_KNOTS + j + 1];
            sseg[(j << 8) + COLP(c)] = make_float2(c0, c1 - c0);
        }
    }

    // ---- per-channel affine params + uniformity check ----
    if (tid < M_CH) {
        const int c = tid;
        const float* kc = knots + c * K_KNOTS;
        float k0 = kc[0];
        float kl = kc[K_KNOTS - 1];
        float h  = (kl - k0) * (1.0f / (float)N_SEG);
        float invh = (float)N_SEG / (kl - k0);
        float tol = 1e-4f * fabsf(h) + 1e-30f;
        bool bad = !(h > 0.0f);
        #pragma unroll 4
        for (int j = 1; j < K_KNOTS - 1; j++) {
            float pred = fmaf((float)j, h, k0);
            if (fabsf(kc[j] - pred) > tol) { bad = true; break; }
        }
        if (bad) *sflag = 1;
        float scale = h / (h + EPS);
        sparam[c] = make_float4(invh, -k0 * invh, scale, 0.0f);
    }
    __syncthreads();

    const bool affine = (*sflag == 0);

    const float4* __restrict__ u4 = (const float4*)u;
    float4*       __restrict__ o4 = (float4*)out;
    const int gtid   = blockIdx.x * blockDim.x + tid;
    const int stride = blockDim.x * gridDim.x;   // group stride; 8*stride % 256 == 0
    const int cb     = (gtid * 8) & (M_CH - 1);  // channels cb..cb+7, fixed

    if (affine) {
        // preload this thread's 8 channel params into registers (R3 verbatim)
        float p_invh[8], p_b[8], p_scale[8];
        #pragma unroll
        for (int i = 0; i < 8; i++) {
            float4 p = sparam[cb + i];
            p_invh[i] = p.x; p_b[i] = p.y; p_scale[i] = p.z;
        }
        // permuted table base for this thread: + (i<<5) + (j<<8) per access
        const float2* __restrict__ seg0 = sseg + (cb >> 3);

        for (int t = gtid; t < n8; t += stride) {
            float4 a = u4[2 * t];
            float4 b = u4[2 * t + 1];
            float x[8] = {a.x, a.y, a.z, a.w, b.x, b.y, b.z, b.w};
            float r[8];
            #pragma unroll
            for (int i = 0; i < 8; i++) {
                float s  = fmaf(x[i], p_invh[i], p_b[i]);
                float jf = floorf(s);
                jf = fminf(fmaxf(jf, 0.0f), (float)(N_SEG - 1));
                int  ji = (int)jf;
                float2 cd = seg0[(ji << 8) + (i << 5)];   // conflict-free LDS.64
                float tt = (s - jf) * p_scale[i];
                r[i] = fmaf(tt, cd.y, cd.x);
            }
            o4[2 * t]     = make_float4(r[0], r[1], r[2], r[3]);
            o4[2 * t + 1] = make_float4(r[4], r[5], r[6], r[7]);
        }
    } else {
        // generic fallback: exact searchsorted-left via binary search on global knots
        for (int t = gtid; t < n8; t += stride) {
            float4 a = u4[2 * t];
            float4 b = u4[2 * t + 1];
            float x[8] = {a.x, a.y, a.z, a.w, b.x, b.y, b.z, b.w};
            float r[8];
            #pragma unroll
            for (int i = 0; i < 8; i++) {
                const int c = cb + i;
                const float* kc = knots + c * K_KNOTS;
                const float xi = x[i];
                int lo = 0, hi = K_KNOTS;
                while (lo < hi) {
                    int mid = (lo + hi) >> 1;
                    if (__ldg(kc + mid) < xi) lo = mid + 1; else hi = mid;
                }
                int j = min(max(lo - 1, 0), N_SEG - 1);
                float k0 = __ldg(kc + j);
                float k1 = __ldg(kc + j + 1);
                float2 cd = sseg[(j << 8) + COLP(c)];
                float tt = (xi - k0) / (k1 - k0 + EPS);
                r[i] = fmaf(tt, cd.y, cd.x);
            }
            o4[2 * t]     = make_float4(r[0], r[1], r[2], r[3]);
            o4[2 * t + 1] = make_float4(r[4], r[5], r[6], r[7]);
        }
    }
}

extern "C" void kernel_launch(void* const* d_in, const int* in_sizes, int n_in,
                              void* d_out, int out_size)
{
    const float* u     = (const float*)d_in[0];
    const float* knots = (const float*)d_in[1];
    const float* coefs = (const float*)d_in[2];
    float*       out   = (float*)d_out;

    const int n  = in_sizes[0];   // 67,108,864 (divisible by 8)
    const int n8 = n >> 3;

    static_assert(SMEM_BYTES <= 227 * 1024, "smem over sm_103a limit");
    cudaFuncSetAttribute(bspline_kernel,
                         cudaFuncAttributeMaxDynamicSharedMemorySize, SMEM_BYTES);

    int dev = 0, nsm = 148;
    cudaGetDevice(&dev);
    cudaDeviceGetAttribute(&nsm, cudaDevAttrMultiProcessorCount, dev);

    bspline_kernel<<<nsm, 1024, SMEM_BYTES>>>(u, knots, coefs, out, n8);
}